// round 5
// baseline (speedup 1.0000x reference)
#include <cuda_runtime.h>
#include <cuda_bf16.h>
#include <cstdint>

#define NTHREADS 256
#define ROWS_PER_BLOCK 512
#define PFEAT 32
#define XS 513   // x_s row stride (mod 32 == 1 -> conflict-free transpose)

typedef unsigned long long u64;

// ---- shared-memory layout (floats); weight bases 16B-aligned ----
#define OFF_WB1T 0        // [32][64] (input-row p zeroed)
#define OFF_WB2T 2048     // [64][32]
#define OFF_WB3T 4096     // [32][32]
#define OFF_WB4T 5120     // [32][16]
#define OFF_WB5T 5632     // [16][8]
#define OFF_WA2T 5760     // [64][32]
#define OFF_WA3T 7808     // [32][16]
#define OFF_WA4T 8320     // [16][8]
#define OFF_WA1  8448     // 64
#define OFF_BA1  8512     // 64
#define OFF_BB1  8576     // 64
#define OFF_BB2  8640     // 32
#define OFF_BB3  8672     // 32
#define OFF_BB4  8704     // 16
#define OFF_BA2  8720     // 32
#define OFF_BA3  8752     // 16
#define OFF_BA4  8768     // 8
#define OFF_BB5  8776     // 8
#define OFF_WB6  8784     // 8
#define OFF_WA5  8792     // 8
#define OFF_BB6  8800     // 1
#define OFF_BA5  8804     // 1
#define W_TOT    8808
#define OFF_XS   8808              // x_s [32][XS]
#define SMEM_FLOATS (W_TOT + 32 * XS)

// ---- f32x2 packed helpers ----
__device__ __forceinline__ u64 pk2(float v) {
    u64 r; asm("mov.b64 %0, {%1, %1};" : "=l"(r) : "f"(v)); return r;
}
__device__ __forceinline__ void upk(float& lo, float& hi, u64 v) {
    asm("mov.b64 {%0, %1}, %2;" : "=f"(lo), "=f"(hi) : "l"(v));
}
__device__ __forceinline__ u64 f2fma(u64 a, u64 b, u64 c) {
    u64 d; asm("fma.rn.f32x2 %0, %1, %2, %3;" : "=l"(d) : "l"(a), "l"(b), "l"(c));
    return d;
}
__device__ __forceinline__ float fast_tanh(float x) {
    float r; asm("tanh.approx.f32 %0, %1;" : "=f"(r) : "f"(x)); return r;
}

// ===== plain packed layer (2 rows share weights); ACT: 0 none, 2 tanh =====
template<int IN, int OUT, int ACT>
__device__ __forceinline__ void layer2(const float* __restrict__ Wt,
                                       const float* __restrict__ B,
                                       const float* in0, const float* in1,
                                       float* out0, float* out1) {
    u64 acc0[OUT / 2], acc1[OUT / 2];
#pragma unroll
    for (int o = 0; o < OUT / 2; o++) {
        u64 b = *reinterpret_cast<const u64*>(B + 2 * o);
        acc0[o] = b; acc1[o] = b;
    }
#pragma unroll
    for (int i = 0; i < IN; i++) {
        const u64 x0 = pk2(in0[i]);
        const u64 x1 = pk2(in1[i]);
#pragma unroll
        for (int o = 0; o < OUT / 2; o += 2) {
            ulonglong2 w = *reinterpret_cast<const ulonglong2*>(Wt + i * OUT + 2 * o);
            acc0[o]     = f2fma(w.x, x0, acc0[o]);
            acc1[o]     = f2fma(w.x, x1, acc1[o]);
            acc0[o + 1] = f2fma(w.y, x0, acc0[o + 1]);
            acc1[o + 1] = f2fma(w.y, x1, acc1[o + 1]);
        }
    }
#pragma unroll
    for (int o = 0; o < OUT / 2; o++) {
        float a, b, c, d;
        upk(a, b, acc0[o]); upk(c, d, acc1[o]);
        if (ACT == 2) { a = fast_tanh(a); b = fast_tanh(b); c = fast_tanh(c); d = fast_tanh(d); }
        out0[2 * o] = a; out0[2 * o + 1] = b;
        out1[2 * o] = c; out1[2 * o + 1] = d;
    }
}

// ===== fused B: layer1 32->64 (relu, x read from smem x_s) streamed into layer2 acc =====
// x0p/x1p point at x_s column for the row; element i at [i*XS].
template<int CHUNK>
__device__ __forceinline__ void fusedB(const float* __restrict__ Wt1,
                                       const float* __restrict__ B1,
                                       const float* __restrict__ Wt2,
                                       const float* __restrict__ x0p,
                                       const float* __restrict__ x1p,
                                       u64* acc2_0, u64* acc2_1) {
#pragma unroll
    for (int c = 0; c < 64; c += CHUNK) {
        u64 m0[CHUNK / 2], m1[CHUNK / 2];
#pragma unroll
        for (int j = 0; j < CHUNK / 2; j++) {
            u64 b = *reinterpret_cast<const u64*>(B1 + c + 2 * j);
            m0[j] = b; m1[j] = b;
        }
#pragma unroll
        for (int i = 0; i < 32; i++) {
            const u64 xx0 = pk2(x0p[i * XS]);
            const u64 xx1 = pk2(x1p[i * XS]);
#pragma unroll
            for (int j = 0; j < CHUNK / 2; j += 2) {
                ulonglong2 w = *reinterpret_cast<const ulonglong2*>(Wt1 + i * 64 + c + 2 * j);
                m0[j]     = f2fma(w.x, xx0, m0[j]);
                m1[j]     = f2fma(w.x, xx1, m1[j]);
                m0[j + 1] = f2fma(w.y, xx0, m0[j + 1]);
                m1[j + 1] = f2fma(w.y, xx1, m1[j + 1]);
            }
        }
#pragma unroll
        for (int j = 0; j < CHUNK / 2; j++) {
            float e, f, g, h;
            upk(e, f, m0[j]); upk(g, h, m1[j]);
            e = fmaxf(e, 0.0f); f = fmaxf(f, 0.0f);
            g = fmaxf(g, 0.0f); h = fmaxf(h, 0.0f);
            const u64 p0 = pk2(e), p1 = pk2(f);
            const u64 q0 = pk2(g), q1 = pk2(h);
            const float* w2a = Wt2 + (c + 2 * j) * 32;
            const float* w2b = w2a + 32;
#pragma unroll
            for (int o = 0; o < 16; o += 2) {
                ulonglong2 wa = *reinterpret_cast<const ulonglong2*>(w2a + 2 * o);
                acc2_0[o]     = f2fma(wa.x, p0, acc2_0[o]);
                acc2_1[o]     = f2fma(wa.x, q0, acc2_1[o]);
                acc2_0[o + 1] = f2fma(wa.y, p0, acc2_0[o + 1]);
                acc2_1[o + 1] = f2fma(wa.y, q0, acc2_1[o + 1]);
                ulonglong2 wb = *reinterpret_cast<const ulonglong2*>(w2b + 2 * o);
                acc2_0[o]     = f2fma(wb.x, p1, acc2_0[o]);
                acc2_1[o]     = f2fma(wb.x, q1, acc2_1[o]);
                acc2_0[o + 1] = f2fma(wb.y, p1, acc2_0[o + 1]);
                acc2_1[o + 1] = f2fma(wb.y, q1, acc2_1[o + 1]);
            }
        }
    }
}

// ===== fused A head: elementwise (w*xs+b, relu) -> layer2 acc =====
__device__ __forceinline__ void fusedA(const float* __restrict__ W1,
                                       const float* __restrict__ B1,
                                       const float* __restrict__ Wt2,
                                       u64 xs0p, u64 xs1p,
                                       u64* acc2_0, u64* acc2_1) {
#pragma unroll
    for (int j = 0; j < 32; j++) {
        u64 w = *reinterpret_cast<const u64*>(W1 + 2 * j);
        u64 b = *reinterpret_cast<const u64*>(B1 + 2 * j);
        u64 m0 = f2fma(w, xs0p, b);
        u64 m1 = f2fma(w, xs1p, b);
        float e, f, g, h;
        upk(e, f, m0); upk(g, h, m1);
        e = fmaxf(e, 0.0f); f = fmaxf(f, 0.0f);
        g = fmaxf(g, 0.0f); h = fmaxf(h, 0.0f);
        const u64 p0 = pk2(e), p1 = pk2(f);
        const u64 q0 = pk2(g), q1 = pk2(h);
        const float* w2a = Wt2 + (2 * j) * 32;
        const float* w2b = w2a + 32;
#pragma unroll
        for (int o = 0; o < 16; o += 2) {
            ulonglong2 wa = *reinterpret_cast<const ulonglong2*>(w2a + 2 * o);
            acc2_0[o]     = f2fma(wa.x, p0, acc2_0[o]);
            acc2_1[o]     = f2fma(wa.x, q0, acc2_1[o]);
            acc2_0[o + 1] = f2fma(wa.y, p0, acc2_0[o + 1]);
            acc2_1[o + 1] = f2fma(wa.y, q0, acc2_1[o + 1]);
            ulonglong2 wb = *reinterpret_cast<const ulonglong2*>(w2b + 2 * o);
            acc2_0[o]     = f2fma(wb.x, p1, acc2_0[o]);
            acc2_1[o]     = f2fma(wb.x, q1, acc2_1[o]);
            acc2_0[o + 1] = f2fma(wb.y, p1, acc2_0[o + 1]);
            acc2_1[o + 1] = f2fma(wb.y, q1, acc2_1[o + 1]);
        }
    }
}

__device__ __forceinline__ float dot8(const float* __restrict__ W, float b,
                                      const float* in) {
    float4 w0 = *reinterpret_cast<const float4*>(W);
    float4 w1 = *reinterpret_cast<const float4*>(W + 4);
    float a = b;
    a = fmaf(w0.x, in[0], a); a = fmaf(w0.y, in[1], a);
    a = fmaf(w0.z, in[2], a); a = fmaf(w0.w, in[3], a);
    a = fmaf(w1.x, in[4], a); a = fmaf(w1.y, in[5], a);
    a = fmaf(w1.z, in[6], a); a = fmaf(w1.w, in[7], a);
    return a;
}

__device__ __forceinline__ void cpy(float* dst, const float* __restrict__ src,
                                    int n, int tid) {
    for (int i = tid; i < n; i += NTHREADS) dst[i] = src[i];
}

template<int IN, int OUT>
__device__ __forceinline__ void stage_t(float* dst, const float* __restrict__ src,
                                        int tid) {
    for (int idx = tid; idx < IN * OUT; idx += NTHREADS) {
        int i = idx / OUT;
        int o = idx & (OUT - 1);
        dst[idx] = src[o * IN + i];
    }
}

__global__ void __launch_bounds__(NTHREADS, 2)
mlp32_kernel(const float* __restrict__ x,
             const float* __restrict__ Wa1, const float* __restrict__ ba1,
             const float* __restrict__ Wa2, const float* __restrict__ ba2,
             const float* __restrict__ Wa3, const float* __restrict__ ba3,
             const float* __restrict__ Wa4, const float* __restrict__ ba4,
             const float* __restrict__ Wa5, const float* __restrict__ ba5,
             const float* __restrict__ Wb1, const float* __restrict__ bb1,
             const float* __restrict__ Wb2, const float* __restrict__ bb2,
             const float* __restrict__ Wb3, const float* __restrict__ bb3,
             const float* __restrict__ Wb4, const float* __restrict__ bb4,
             const float* __restrict__ Wb5, const float* __restrict__ bb5,
             const float* __restrict__ Wb6, const float* __restrict__ bb6,
             float* __restrict__ out, int nrows) {
    extern __shared__ float s[];
    float* xs_ = s + OFF_XS;
    const int p = blockIdx.y;
    const int tid = threadIdx.x;

    // ---- stage weights (transposed) ----
    for (int idx = tid; idx < 32 * 64; idx += NTHREADS) {
        int i = idx >> 6, o = idx & 63;
        float v = 0.0f;
        if (i < p)      v = Wb1[(p * 64 + o) * 31 + i];
        else if (i > p) v = Wb1[(p * 64 + o) * 31 + i - 1];
        s[OFF_WB1T + idx] = v;
    }
    stage_t<64, 32>(s + OFF_WB2T, Wb2 + p * 32 * 64, tid);
    stage_t<32, 32>(s + OFF_WB3T, Wb3 + p * 32 * 32, tid);
    stage_t<32, 16>(s + OFF_WB4T, Wb4 + p * 16 * 32, tid);
    stage_t<16, 8>(s + OFF_WB5T, Wb5 + p * 8 * 16, tid);
    stage_t<64, 32>(s + OFF_WA2T, Wa2 + p * 32 * 64, tid);
    stage_t<32, 16>(s + OFF_WA3T, Wa3 + p * 16 * 32, tid);
    stage_t<16, 8>(s + OFF_WA4T, Wa4 + p * 8 * 16, tid);
    cpy(s + OFF_WA1, Wa1 + p * 64, 64, tid);
    cpy(s + OFF_BA1, ba1 + p * 64, 64, tid);
    cpy(s + OFF_BB1, bb1 + p * 64, 64, tid);
    cpy(s + OFF_BB2, bb2 + p * 32, 32, tid);
    cpy(s + OFF_BB3, bb3 + p * 32, 32, tid);
    cpy(s + OFF_BB4, bb4 + p * 16, 16, tid);
    cpy(s + OFF_BA2, ba2 + p * 32, 32, tid);
    cpy(s + OFF_BA3, ba3 + p * 16, 16, tid);
    cpy(s + OFF_BA4, ba4 + p * 8, 8, tid);
    cpy(s + OFF_BB5, bb5 + p * 8, 8, tid);
    cpy(s + OFF_WB6, Wb6 + p * 8, 8, tid);
    cpy(s + OFF_WA5, Wa5 + p * 8, 8, tid);
    if (tid == 0) {
        s[OFF_BB6] = bb6[p];
        s[OFF_BA5] = ba5[p];
    }

    // ---- stage x tile transposed: x_s[i][r] = x[R0+r][i] ----
    const int R0 = blockIdx.x * ROWS_PER_BLOCK;
    const float4* x4 = reinterpret_cast<const float4*>(x);
#pragma unroll
    for (int k = 0; k < (ROWS_PER_BLOCK * 8) / NTHREADS; k++) {
        int idx = tid + k * NTHREADS;
        int r = idx >> 3, i4 = idx & 7;
        float4 v = make_float4(0.f, 0.f, 0.f, 0.f);
        if (R0 + r < nrows) v = x4[(R0 + r) * 8 + i4];
        xs_[(4 * i4 + 0) * XS + r] = v.x;
        xs_[(4 * i4 + 1) * XS + r] = v.y;
        xs_[(4 * i4 + 2) * XS + r] = v.z;
        xs_[(4 * i4 + 3) * XS + r] = v.w;
    }
    __syncthreads();

    const int row0 = R0 + tid;
    const int row1 = row0 + NTHREADS;
    const float* x0p = xs_ + tid;
    const float* x1p = xs_ + tid + NTHREADS;

    // ---- encoder B: fused (32->64 relu ->32 acc), tanh, 32->32, 32->16, 16->8, dot ----
    float h2a[32], h2b[32];
    {
        u64 acc0[16], acc1[16];
#pragma unroll
        for (int o = 0; o < 16; o++) {
            u64 b = *reinterpret_cast<const u64*>(s + OFF_BB2 + 2 * o);
            acc0[o] = b; acc1[o] = b;
        }
        fusedB<16>(s + OFF_WB1T, s + OFF_BB1, s + OFF_WB2T, x0p, x1p, acc0, acc1);
#pragma unroll
        for (int o = 0; o < 16; o++) {
            float a, b, c, d;
            upk(a, b, acc0[o]); upk(c, d, acc1[o]);
            h2a[2 * o] = fast_tanh(a); h2a[2 * o + 1] = fast_tanh(b);
            h2b[2 * o] = fast_tanh(c); h2b[2 * o + 1] = fast_tanh(d);
        }
    }
    float h3a[32], h3b[32];
    layer2<32, 32, 2>(s + OFF_WB3T, s + OFF_BB3, h2a, h2b, h3a, h3b);
    float h4a[16], h4b[16];
    layer2<32, 16, 2>(s + OFF_WB4T, s + OFF_BB4, h3a, h3b, h4a, h4b);
    float h5a[8], h5b[8];
    layer2<16, 8, 0>(s + OFF_WB5T, s + OFF_BB5, h4a, h4b, h5a, h5b);
    const float bOut0 = dot8(s + OFF_WB6, s[OFF_BB6], h5a);
    const float bOut1 = dot8(s + OFF_WB6, s[OFF_BB6], h5b);

    // ---- encoder A: fused (1->64 relu ->32 acc), tanh, 32->16, 16->8, dot ----
    float a2a[32], a2b[32];
    {
        u64 acc0[16], acc1[16];
#pragma unroll
        for (int o = 0; o < 16; o++) {
            u64 b = *reinterpret_cast<const u64*>(s + OFF_BA2 + 2 * o);
            acc0[o] = b; acc1[o] = b;
        }
        fusedA(s + OFF_WA1, s + OFF_BA1, s + OFF_WA2T,
               pk2(x0p[p * XS]), pk2(x1p[p * XS]), acc0, acc1);
#pragma unroll
        for (int o = 0; o < 16; o++) {
            float a, b, c, d;
            upk(a, b, acc0[o]); upk(c, d, acc1[o]);
            a2a[2 * o] = fast_tanh(a); a2a[2 * o + 1] = fast_tanh(b);
            a2b[2 * o] = fast_tanh(c); a2b[2 * o + 1] = fast_tanh(d);
        }
    }
    float a3a[16], a3b[16];
    layer2<32, 16, 2>(s + OFF_WA3T, s + OFF_BA3, a2a, a2b, a3a, a3b);
    float a4a[8], a4b[8];
    layer2<16, 8, 2>(s + OFF_WA4T, s + OFF_BA4, a3a, a3b, a4a, a4b);
    const float aOut0 = dot8(s + OFF_WA5, s[OFF_BA5], a4a);
    const float aOut1 = dot8(s + OFF_WA5, s[OFF_BA5], a4b);

    if (row0 < nrows) {
        out[row0 * 64 + 2 * p + 0] = aOut0;
        out[row0 * 64 + 2 * p + 1] = bOut0;
    }
    if (row1 < nrows) {
        out[row1 * 64 + 2 * p + 0] = aOut1;
        out[row1 * 64 + 2 * p + 1] = bOut1;
    }
}

extern "C" void kernel_launch(void* const* d_in, const int* in_sizes, int n_in,
                              void* d_out, int out_size) {
    const float* x   = (const float*)d_in[0];
    const float* Wa1 = (const float*)d_in[1];
    const float* ba1 = (const float*)d_in[2];
    const float* Wa2 = (const float*)d_in[3];
    const float* ba2 = (const float*)d_in[4];
    const float* Wa3 = (const float*)d_in[5];
    const float* ba3 = (const float*)d_in[6];
    const float* Wa4 = (const float*)d_in[7];
    const float* ba4 = (const float*)d_in[8];
    const float* Wa5 = (const float*)d_in[9];
    const float* ba5 = (const float*)d_in[10];
    const float* Wb1 = (const float*)d_in[11];
    const float* bb1 = (const float*)d_in[12];
    const float* Wb2 = (const float*)d_in[13];
    const float* bb2 = (const float*)d_in[14];
    const float* Wb3 = (const float*)d_in[15];
    const float* bb3 = (const float*)d_in[16];
    const float* Wb4 = (const float*)d_in[17];
    const float* bb4 = (const float*)d_in[18];
    const float* Wb5 = (const float*)d_in[19];
    const float* bb5 = (const float*)d_in[20];
    const float* Wb6 = (const float*)d_in[21];
    const float* bb6 = (const float*)d_in[22];
    float* out = (float*)d_out;

    const int nrows = in_sizes[0] / PFEAT;
    const size_t smemBytes = SMEM_FLOATS * sizeof(float);
    static bool configured = false;
    if (!configured) {
        cudaFuncSetAttribute(mlp32_kernel,
                             cudaFuncAttributeMaxDynamicSharedMemorySize,
                             (int)smemBytes);
        configured = true;
    }
    dim3 grid((nrows + ROWS_PER_BLOCK - 1) / ROWS_PER_BLOCK, PFEAT);
    mlp32_kernel<<<grid, NTHREADS, smemBytes>>>(
        x, Wa1, ba1, Wa2, ba2, Wa3, ba3, Wa4, ba4, Wa5, ba5,
        Wb1, bb1, Wb2, bb2, Wb3, bb3, Wb4, bb4, Wb5, bb5, Wb6, bb6,
        out, nrows);
}

// round 6
// speedup vs baseline: 1.0170x; 1.0170x over previous
#include <cuda_runtime.h>
#include <cuda_bf16.h>
#include <cstdint>

#define NTHREADS 128
#define RPT 2
#define PFEAT 32

typedef unsigned long long u64;

// ---- shared-memory layout (floats); weight bases 16B-aligned ----
#define OFF_WB1T 0        // [32][64] (input-row p zeroed)
#define OFF_WB2T 2048     // [64][32]
#define OFF_WB3T 4096     // [32][32]
#define OFF_WB4T 5120     // [32][16]
#define OFF_WB5T 5632     // [16][8]
#define OFF_WA2T 5760     // [64][32]
#define OFF_WA3T 7808     // [32][16]
#define OFF_WA4T 8320     // [16][8]
#define OFF_WA1  8448     // 64
#define OFF_BA1  8512     // 64
#define OFF_BB1  8576     // 64
#define OFF_BB2  8640     // 32
#define OFF_BB3  8672     // 32
#define OFF_BB4  8704     // 16
#define OFF_BA2  8720     // 32
#define OFF_BA3  8752     // 16
#define OFF_BA4  8768     // 8
#define OFF_BB5  8776     // 8
#define OFF_WB6  8784     // 8
#define OFF_WA5  8792     // 8
#define OFF_BB6  8800     // 1
#define OFF_BA5  8804     // 1
#define SMEM_TOT 8808

// ---- f32x2 packed helpers ----
__device__ __forceinline__ u64 pk2(float v) {
    u64 r; asm("mov.b64 %0, {%1, %1};" : "=l"(r) : "f"(v)); return r;
}
__device__ __forceinline__ void upk(float& lo, float& hi, u64 v) {
    asm("mov.b64 {%0, %1}, %2;" : "=f"(lo), "=f"(hi) : "l"(v));
}
__device__ __forceinline__ u64 f2fma(u64 a, u64 b, u64 c) {
    u64 d; asm("fma.rn.f32x2 %0, %1, %2, %3;" : "=l"(d) : "l"(a), "l"(b), "l"(c));
    return d;
}
__device__ __forceinline__ float fast_tanh(float x) {
    float r; asm("tanh.approx.f32 %0, %1;" : "=f"(r) : "f"(x)); return r;
}

// ===== packed->packed layer: consumes packed pre-activation inputs, applies
// ACTIN (0 none, 2 tanh) to inputs inline per-pair, produces packed RAW acc. =====
template<int IN, int OUT, int ACTIN>
__device__ __forceinline__ void layerP(const float* __restrict__ Wt,
                                       const float* __restrict__ B,
                                       const u64* in0, const u64* in1,
                                       u64* acc0, u64* acc1) {
#pragma unroll
    for (int o = 0; o < OUT / 2; o++) {
        u64 b = *reinterpret_cast<const u64*>(B + 2 * o);
        acc0[o] = b; acc1[o] = b;
    }
#pragma unroll
    for (int ip = 0; ip < IN / 2; ip++) {
        float e, f, g, h;
        upk(e, f, in0[ip]); upk(g, h, in1[ip]);
        if (ACTIN == 2) { e = fast_tanh(e); f = fast_tanh(f); g = fast_tanh(g); h = fast_tanh(h); }
        const u64 x0a = pk2(e), x0b = pk2(f);
        const u64 x1a = pk2(g), x1b = pk2(h);
        const float* wA = Wt + (2 * ip) * OUT;
        const float* wB = wA + OUT;
#pragma unroll
        for (int o = 0; o < OUT / 2; o += 2) {
            ulonglong2 wa = *reinterpret_cast<const ulonglong2*>(wA + 2 * o);
            acc0[o]     = f2fma(wa.x, x0a, acc0[o]);
            acc1[o]     = f2fma(wa.x, x1a, acc1[o]);
            acc0[o + 1] = f2fma(wa.y, x0a, acc0[o + 1]);
            acc1[o + 1] = f2fma(wa.y, x1a, acc1[o + 1]);
            ulonglong2 wb = *reinterpret_cast<const ulonglong2*>(wB + 2 * o);
            acc0[o]     = f2fma(wb.x, x0b, acc0[o]);
            acc1[o]     = f2fma(wb.x, x1b, acc1[o]);
            acc0[o + 1] = f2fma(wb.y, x0b, acc0[o + 1]);
            acc1[o + 1] = f2fma(wb.y, x1b, acc1[o + 1]);
        }
    }
}

// ===== final dot: packed input (IN/2 u64 per row) + ACTIN, scalar out per row =====
template<int IN, int ACTIN>
__device__ __forceinline__ void dotP(const float* __restrict__ W, float b,
                                     const u64* in0, const u64* in1,
                                     float& r0, float& r1) {
    float a0 = b, a1 = b;
#pragma unroll
    for (int ip = 0; ip < IN / 2; ip++) {
        float e, f, g, h;
        upk(e, f, in0[ip]); upk(g, h, in1[ip]);
        if (ACTIN == 2) { e = fast_tanh(e); f = fast_tanh(f); g = fast_tanh(g); h = fast_tanh(h); }
        const float w0 = W[2 * ip], w1 = W[2 * ip + 1];
        a0 = fmaf(w0, e, a0); a0 = fmaf(w1, f, a0);
        a1 = fmaf(w0, g, a1); a1 = fmaf(w1, h, a1);
    }
    r0 = a0; r1 = a1;
}

// ===== fused B: layer1 32->64 (relu inline) streamed in CHUNKs into layer2 acc (raw) =====
template<int CHUNK>
__device__ __forceinline__ void fusedB(const float* __restrict__ Wt1,
                                       const float* __restrict__ B1,
                                       const float* __restrict__ Wt2,
                                       const float* in0, const float* in1,
                                       u64* acc2_0, u64* acc2_1) {
#pragma unroll
    for (int c = 0; c < 64; c += CHUNK) {
        u64 m0[CHUNK / 2], m1[CHUNK / 2];
#pragma unroll
        for (int j = 0; j < CHUNK / 2; j++) {
            u64 b = *reinterpret_cast<const u64*>(B1 + c + 2 * j);
            m0[j] = b; m1[j] = b;
        }
#pragma unroll
        for (int i = 0; i < 32; i++) {
            const u64 xx0 = pk2(in0[i]);
            const u64 xx1 = pk2(in1[i]);
#pragma unroll
            for (int j = 0; j < CHUNK / 2; j += 2) {
                ulonglong2 w = *reinterpret_cast<const ulonglong2*>(Wt1 + i * 64 + c + 2 * j);
                m0[j]     = f2fma(w.x, xx0, m0[j]);
                m1[j]     = f2fma(w.x, xx1, m1[j]);
                m0[j + 1] = f2fma(w.y, xx0, m0[j + 1]);
                m1[j + 1] = f2fma(w.y, xx1, m1[j + 1]);
            }
        }
#pragma unroll
        for (int j = 0; j < CHUNK / 2; j++) {
            float e, f, g, h;
            upk(e, f, m0[j]); upk(g, h, m1[j]);
            e = fmaxf(e, 0.0f); f = fmaxf(f, 0.0f);
            g = fmaxf(g, 0.0f); h = fmaxf(h, 0.0f);
            const u64 p0 = pk2(e), p1 = pk2(f);
            const u64 q0 = pk2(g), q1 = pk2(h);
            const float* w2a = Wt2 + (c + 2 * j) * 32;
            const float* w2b = w2a + 32;
#pragma unroll
            for (int o = 0; o < 16; o += 2) {
                ulonglong2 wa = *reinterpret_cast<const ulonglong2*>(w2a + 2 * o);
                acc2_0[o]     = f2fma(wa.x, p0, acc2_0[o]);
                acc2_1[o]     = f2fma(wa.x, q0, acc2_1[o]);
                acc2_0[o + 1] = f2fma(wa.y, p0, acc2_0[o + 1]);
                acc2_1[o + 1] = f2fma(wa.y, q0, acc2_1[o + 1]);
                ulonglong2 wb = *reinterpret_cast<const ulonglong2*>(w2b + 2 * o);
                acc2_0[o]     = f2fma(wb.x, p1, acc2_0[o]);
                acc2_1[o]     = f2fma(wb.x, q1, acc2_1[o]);
                acc2_0[o + 1] = f2fma(wb.y, p1, acc2_0[o + 1]);
                acc2_1[o + 1] = f2fma(wb.y, q1, acc2_1[o + 1]);
            }
        }
    }
}

// ===== fused A head: elementwise (w*xs+b, relu) -> layer2 acc (raw) =====
__device__ __forceinline__ void fusedA(const float* __restrict__ W1,
                                       const float* __restrict__ B1,
                                       const float* __restrict__ Wt2,
                                       u64 xs0p, u64 xs1p,
                                       u64* acc2_0, u64* acc2_1) {
#pragma unroll
    for (int j = 0; j < 32; j++) {
        u64 w = *reinterpret_cast<const u64*>(W1 + 2 * j);
        u64 b = *reinterpret_cast<const u64*>(B1 + 2 * j);
        u64 m0 = f2fma(w, xs0p, b);
        u64 m1 = f2fma(w, xs1p, b);
        float e, f, g, h;
        upk(e, f, m0); upk(g, h, m1);
        e = fmaxf(e, 0.0f); f = fmaxf(f, 0.0f);
        g = fmaxf(g, 0.0f); h = fmaxf(h, 0.0f);
        const u64 p0 = pk2(e), p1 = pk2(f);
        const u64 q0 = pk2(g), q1 = pk2(h);
        const float* w2a = Wt2 + (2 * j) * 32;
        const float* w2b = w2a + 32;
#pragma unroll
        for (int o = 0; o < 16; o += 2) {
            ulonglong2 wa = *reinterpret_cast<const ulonglong2*>(w2a + 2 * o);
            acc2_0[o]     = f2fma(wa.x, p0, acc2_0[o]);
            acc2_1[o]     = f2fma(wa.x, q0, acc2_1[o]);
            acc2_0[o + 1] = f2fma(wa.y, p0, acc2_0[o + 1]);
            acc2_1[o + 1] = f2fma(wa.y, q0, acc2_1[o + 1]);
            ulonglong2 wb = *reinterpret_cast<const ulonglong2*>(w2b + 2 * o);
            acc2_0[o]     = f2fma(wb.x, p1, acc2_0[o]);
            acc2_1[o]     = f2fma(wb.x, q1, acc2_1[o]);
            acc2_0[o + 1] = f2fma(wb.y, p1, acc2_0[o + 1]);
            acc2_1[o + 1] = f2fma(wb.y, q1, acc2_1[o + 1]);
        }
    }
}

__device__ __forceinline__ void cpy(float* dst, const float* __restrict__ src,
                                    int n, int tid) {
    for (int i = tid; i < n; i += NTHREADS) dst[i] = src[i];
}

template<int IN, int OUT>
__device__ __forceinline__ void stage_t(float* dst, const float* __restrict__ src,
                                        int tid) {
    for (int idx = tid; idx < IN * OUT; idx += NTHREADS) {
        int i = idx / OUT;
        int o = idx & (OUT - 1);
        dst[idx] = src[o * IN + i];
    }
}

__global__ void __launch_bounds__(NTHREADS, 3)
mlp32_kernel(const float* __restrict__ x,
             const float* __restrict__ Wa1, const float* __restrict__ ba1,
             const float* __restrict__ Wa2, const float* __restrict__ ba2,
             const float* __restrict__ Wa3, const float* __restrict__ ba3,
             const float* __restrict__ Wa4, const float* __restrict__ ba4,
             const float* __restrict__ Wa5, const float* __restrict__ ba5,
             const float* __restrict__ Wb1, const float* __restrict__ bb1,
             const float* __restrict__ Wb2, const float* __restrict__ bb2,
             const float* __restrict__ Wb3, const float* __restrict__ bb3,
             const float* __restrict__ Wb4, const float* __restrict__ bb4,
             const float* __restrict__ Wb5, const float* __restrict__ bb5,
             const float* __restrict__ Wb6, const float* __restrict__ bb6,
             float* __restrict__ out, int nrows) {
    __shared__ float s[SMEM_TOT];
    const int p = blockIdx.y;
    const int tid = threadIdx.x;

    // ---- stage weights (transposed) ----
    for (int idx = tid; idx < 32 * 64; idx += NTHREADS) {
        int i = idx >> 6, o = idx & 63;
        float v = 0.0f;
        if (i < p)      v = Wb1[(p * 64 + o) * 31 + i];
        else if (i > p) v = Wb1[(p * 64 + o) * 31 + i - 1];
        s[OFF_WB1T + idx] = v;
    }
    stage_t<64, 32>(s + OFF_WB2T, Wb2 + p * 32 * 64, tid);
    stage_t<32, 32>(s + OFF_WB3T, Wb3 + p * 32 * 32, tid);
    stage_t<32, 16>(s + OFF_WB4T, Wb4 + p * 16 * 32, tid);
    stage_t<16, 8>(s + OFF_WB5T, Wb5 + p * 8 * 16, tid);
    stage_t<64, 32>(s + OFF_WA2T, Wa2 + p * 32 * 64, tid);
    stage_t<32, 16>(s + OFF_WA3T, Wa3 + p * 16 * 32, tid);
    stage_t<16, 8>(s + OFF_WA4T, Wa4 + p * 8 * 16, tid);
    cpy(s + OFF_WA1, Wa1 + p * 64, 64, tid);
    cpy(s + OFF_BA1, ba1 + p * 64, 64, tid);
    cpy(s + OFF_BB1, bb1 + p * 64, 64, tid);
    cpy(s + OFF_BB2, bb2 + p * 32, 32, tid);
    cpy(s + OFF_BB3, bb3 + p * 32, 32, tid);
    cpy(s + OFF_BB4, bb4 + p * 16, 16, tid);
    cpy(s + OFF_BA2, ba2 + p * 32, 32, tid);
    cpy(s + OFF_BA3, ba3 + p * 16, 16, tid);
    cpy(s + OFF_BA4, ba4 + p * 8, 8, tid);
    cpy(s + OFF_BB5, bb5 + p * 8, 8, tid);
    cpy(s + OFF_WB6, Wb6 + p * 8, 8, tid);
    cpy(s + OFF_WA5, Wa5 + p * 8, 8, tid);
    if (tid == 0) {
        s[OFF_BB6] = bb6[p];
        s[OFF_BA5] = ba5[p];
    }
    __syncthreads();

    const int blockBase = blockIdx.x * (NTHREADS * 2 * RPT);

#pragma unroll 1
    for (int r = 0; r < RPT; ++r) {
        const int row0 = blockBase + r * (2 * NTHREADS) + tid;
        const int row1 = row0 + NTHREADS;
        if (row0 >= nrows) break;
        const bool has1 = (row1 < nrows);

        float xr0[32], xr1[32];
        {
            const float4* xv0 = reinterpret_cast<const float4*>(x) + row0 * 8;
#pragma unroll
            for (int q = 0; q < 8; q++) {
                float4 v = xv0[q];
                xr0[4 * q] = v.x; xr0[4 * q + 1] = v.y;
                xr0[4 * q + 2] = v.z; xr0[4 * q + 3] = v.w;
            }
            if (has1) {
                const float4* xv1 = reinterpret_cast<const float4*>(x) + row1 * 8;
#pragma unroll
                for (int q = 0; q < 8; q++) {
                    float4 v = xv1[q];
                    xr1[4 * q] = v.x; xr1[4 * q + 1] = v.y;
                    xr1[4 * q + 2] = v.z; xr1[4 * q + 3] = v.w;
                }
            } else {
#pragma unroll
                for (int q = 0; q < 32; q++) xr1[q] = 0.0f;
            }
        }
        const float xs0 = xr0[p];
        const float xs1 = xr1[p];

        // ---- encoder B: fused (32->64 relu ->32 raw), then packed layers with
        //      input-side tanh: ->32 ->16 ->8 (no out act), dot ----
        float bOut0, bOut1;
        {
            u64 acc2a[16], acc2b[16];
#pragma unroll
            for (int o = 0; o < 16; o++) {
                u64 b = *reinterpret_cast<const u64*>(s + OFF_BB2 + 2 * o);
                acc2a[o] = b; acc2b[o] = b;
            }
            fusedB<8>(s + OFF_WB1T, s + OFF_BB1, s + OFF_WB2T, xr0, xr1, acc2a, acc2b);
            u64 h3a[16], h3b[16];
            layerP<32, 32, 2>(s + OFF_WB3T, s + OFF_BB3, acc2a, acc2b, h3a, h3b);
            u64 h4a[8], h4b[8];
            layerP<32, 16, 2>(s + OFF_WB4T, s + OFF_BB4, h3a, h3b, h4a, h4b);
            u64 h5a[4], h5b[4];
            layerP<16, 8, 2>(s + OFF_WB5T, s + OFF_BB5, h4a, h4b, h5a, h5b);
            dotP<8, 0>(s + OFF_WB6, s[OFF_BB6], h5a, h5b, bOut0, bOut1);
        }

        // ---- encoder A: fused (1->64 relu ->32 raw), ->16, ->8, dot (tanh-in) ----
        float aOut0, aOut1;
        {
            u64 acc2a[16], acc2b[16];
#pragma unroll
            for (int o = 0; o < 16; o++) {
                u64 b = *reinterpret_cast<const u64*>(s + OFF_BA2 + 2 * o);
                acc2a[o] = b; acc2b[o] = b;
            }
            fusedA(s + OFF_WA1, s + OFF_BA1, s + OFF_WA2T,
                   pk2(xs0), pk2(xs1), acc2a, acc2b);
            u64 a3a[8], a3b[8];
            layerP<32, 16, 2>(s + OFF_WA3T, s + OFF_BA3, acc2a, acc2b, a3a, a3b);
            u64 a4a[4], a4b[4];
            layerP<16, 8, 2>(s + OFF_WA4T, s + OFF_BA4, a3a, a3b, a4a, a4b);
            dotP<8, 2>(s + OFF_WA5, s[OFF_BA5], a4a, a4b, aOut0, aOut1);
        }

        out[row0 * 64 + 2 * p + 0] = aOut0;
        out[row0 * 64 + 2 * p + 1] = bOut0;
        if (has1) {
            out[row1 * 64 + 2 * p + 0] = aOut1;
            out[row1 * 64 + 2 * p + 1] = bOut1;
        }
    }
}

extern "C" void kernel_launch(void* const* d_in, const int* in_sizes, int n_in,
                              void* d_out, int out_size) {
    const float* x   = (const float*)d_in[0];
    const float* Wa1 = (const float*)d_in[1];
    const float* ba1 = (const float*)d_in[2];
    const float* Wa2 = (const float*)d_in[3];
    const float* ba2 = (const float*)d_in[4];
    const float* Wa3 = (const float*)d_in[5];
    const float* ba3 = (const float*)d_in[6];
    const float* Wa4 = (const float*)d_in[7];
    const float* ba4 = (const float*)d_in[8];
    const float* Wa5 = (const float*)d_in[9];
    const float* ba5 = (const float*)d_in[10];
    const float* Wb1 = (const float*)d_in[11];
    const float* bb1 = (const float*)d_in[12];
    const float* Wb2 = (const float*)d_in[13];
    const float* bb2 = (const float*)d_in[14];
    const float* Wb3 = (const float*)d_in[15];
    const float* bb3 = (const float*)d_in[16];
    const float* Wb4 = (const float*)d_in[17];
    const float* bb4 = (const float*)d_in[18];
    const float* Wb5 = (const float*)d_in[19];
    const float* bb5 = (const float*)d_in[20];
    const float* Wb6 = (const float*)d_in[21];
    const float* bb6 = (const float*)d_in[22];
    float* out = (float*)d_out;

    const int nrows = in_sizes[0] / PFEAT;
    const int rowsPerBlock = NTHREADS * 2 * RPT;
    dim3 grid((nrows + rowsPerBlock - 1) / rowsPerBlock, PFEAT);
    mlp32_kernel<<<grid, NTHREADS>>>(
        x, Wa1, ba1, Wa2, ba2, Wa3, ba3, Wa4, ba4, Wa5, ba5,
        Wb1, bb1, Wb2, bb2, Wb3, bb3, Wb4, bb4, Wb5, bb5, Wb6, bb6,
        out, nrows);
}